// round 12
// baseline (speedup 1.0000x reference)
#include <cuda_runtime.h>
#include <cuda_bf16.h>
#include <math.h>
#include <stdint.h>

// ---------------- problem constants ----------------
#define BSZ 2
#define HH  48
#define WW  48
#define LL  (HH*WW)          // 2304
#define CIN 384              // 2*D_MODEL
#define CC  768              // C_INNER
#define KG  4
#define DD  192              // D_IN
#define NS  16
#define RR  12
#define CDBL 44              // R + 2N
#define BL  (BSZ*LL)         // 4608
#define NCH 16
#define CHL (LL/NCH)         // 144
#define NBKD (BSZ*KG*DD)     // 1536

// ---------------- device scratch ----------------
__device__ float g_xz  [BL*CC];          // in_proj output, [B*L, 768] channel-last
__device__ float g_xs  [BSZ*KG*DD*LL];   // scan inputs u, [bkd][L]
__device__ float g_B   [BSZ*KG*LL*NS];   // B, [bk][l][n]  (n fastest)
__device__ float g_C   [BSZ*KG*LL*NS];   // C, [bk][l][n]
__device__ float g_dt  [BSZ*KG*DD*LL];   // softplus(dt), [bkd][L]
__device__ float g_ym  [BL*CC];          // y merged spatially, [B*L, 768]

// bf16 split operand buffers for tensor-core GEMMs
__device__ __nv_bfloat16 g_xh [BL*CIN],  g_xm [BL*CIN];   // x split
__device__ __nv_bfloat16 g_wih[CC*CIN],  g_wim[CC*CIN];   // in_proj_w split
__device__ __nv_bfloat16 g_woh[CIN*CC],  g_wom[CIN*CC];   // out_proj_w split
__device__ __nv_bfloat16 g_ylh[BL*CC],   g_ylm[BL*CC];    // layernorm output split

// scan-order index -> spatial index, per direction k
__device__ __forceinline__ int lsp_of(int k, int l) {
    switch (k) {
        case 0:  return l;
        case 1:  return (l % HH) * WW + (l / HH);
        case 2:  return LL - 1 - l;
        default: { int l2 = LL - 1 - l; return (l2 % HH) * WW + (l2 / HH); }
    }
}

__device__ __forceinline__ float softplusf(float x) {
    return (x > 15.f) ? x : log1pf(__expf(x));
}

__device__ __forceinline__ uint32_t smem_u32(const void* p) {
    return (uint32_t)__cvta_generic_to_shared(p);
}

__device__ __forceinline__ void cp16(uint32_t saddr, const void* g) {
    asm volatile("cp.async.cg.shared.global [%0], [%1], 16;" :: "r"(saddr), "l"(g));
}
__device__ __forceinline__ void cp_commit() {
    asm volatile("cp.async.commit_group;");
}
__device__ __forceinline__ void cp_wait1() {
    asm volatile("cp.async.wait_group 1;");
}

// ---------------- fused bf16 split (x, in_proj_w, out_proj_w) ---------------
__global__ void k_split3(const float* __restrict__ x,
                         const float* __restrict__ ipw,
                         const float* __restrict__ opw) {
    const int n1 = BL * CIN, n2 = n1 + CC * CIN, n3 = n2 + CIN * CC;
    int i = blockIdx.x * blockDim.x + threadIdx.x;
    if (i >= n3) return;
    const float* s; __nv_bfloat16 *hp, *mp; int off;
    if (i < n1)      { s = x;   hp = g_xh;  mp = g_xm;  off = i; }
    else if (i < n2) { s = ipw; hp = g_wih; mp = g_wim; off = i - n1; }
    else             { s = opw; hp = g_woh; mp = g_wom; off = i - n2; }
    float v = s[off];
    __nv_bfloat16 h = __float2bfloat16(v);
    hp[off] = h;
    mp[off] = __float2bfloat16(v - __bfloat162float(h));
}

// ---------------- bf16 3-split tensor-core GEMM (NT) ------------------------
// R8 measured-best config. C[M,N]=A*B^T via Ah*Bh + Ah*Bm + Am*Bh, fp32 accum.
// Warp tile 64x32 (MT=4 x NT=4), ldmatrix frags, cp.async 2-stage pipeline.

#define SROW 12   // smem row stride in words (8 data + 4 pad)

#define MMA_BF16(C, a0,a1,a2,a3, b0,b1) \
    asm volatile("mma.sync.aligned.m16n8k16.row.col.f32.bf16.bf16.f32 " \
        "{%0,%1,%2,%3},{%4,%5,%6,%7},{%8,%9},{%0,%1,%2,%3};" \
        : "+f"(C[0]), "+f"(C[1]), "+f"(C[2]), "+f"(C[3]) \
        : "r"(a0), "r"(a1), "r"(a2), "r"(a3), "r"(b0), "r"(b1))

#define LDSM4(r0,r1,r2,r3,addr) \
    asm volatile("ldmatrix.sync.aligned.m8n8.x4.shared.b16 {%0,%1,%2,%3}, [%4];" \
        : "=r"(r0), "=r"(r1), "=r"(r2), "=r"(r3) : "r"(addr))

template<int BM, int BN, int NTHR, int WR>
__device__ __forceinline__ void gemm_body(int N, int Kd,
        const __nv_bfloat16* __restrict__ Ahp, const __nv_bfloat16* __restrict__ Amp,
        const __nv_bfloat16* __restrict__ Bhp, const __nv_bfloat16* __restrict__ Bmp,
        float* __restrict__ Co) {
    constexpr int MT = BM / (WR * 16);      // 4
    __shared__ uint32_t sAh[2][BM * SROW], sAm[2][BM * SROW];
    __shared__ uint32_t sBh[2][BN * SROW], sBm[2][BN * SROW];

    const int tid  = threadIdx.x;
    const int lane = tid & 31;
    const int wid  = tid >> 5;
    const int g    = lane >> 2;
    const int t    = lane & 3;
    const int wm   = (wid % WR) * (MT * 16);
    const int wn   = (wid / WR) * 32;
    const int bm0  = blockIdx.y * BM;
    const int bn0  = blockIdx.x * BN;
    const int Kw   = Kd >> 1;

    const uint32_t* gAh = (const uint32_t*)Ahp;
    const uint32_t* gAm = (const uint32_t*)Amp;
    const uint32_t* gBh = (const uint32_t*)Bhp;
    const uint32_t* gBm = (const uint32_t*)Bmp;

    const int lrow8 = ((lane >> 3) & 1) * 8 + (lane & 7);
    const int loff  = (lane >> 4) * 4;

    float acc[MT][4][4];
#pragma unroll
    for (int mt = 0; mt < MT; mt++)
#pragma unroll
        for (int nt = 0; nt < 4; nt++)
#pragma unroll
            for (int j = 0; j < 4; j++) acc[mt][nt][j] = 0.f;

    auto load_stage = [&](int kt, int st) {
        const int k0w = kt * 8;
#pragma unroll
        for (int idx = tid; idx < 2 * (BM + BN); idx += NTHR) {
            int half = idx & 1, r = idx >> 1;
            if (r < BM) {
                cp16(smem_u32(&sAh[st][r * SROW + half * 4]),
                     &gAh[(bm0 + r) * Kw + k0w + half * 4]);
                cp16(smem_u32(&sAm[st][r * SROW + half * 4]),
                     &gAm[(bm0 + r) * Kw + k0w + half * 4]);
            } else {
                int rb = r - BM;
                cp16(smem_u32(&sBh[st][rb * SROW + half * 4]),
                     &gBh[(bn0 + rb) * Kw + k0w + half * 4]);
                cp16(smem_u32(&sBm[st][rb * SROW + half * 4]),
                     &gBm[(bn0 + rb) * Kw + k0w + half * 4]);
            }
        }
    };

    const int NKT = Kw / 8;
    load_stage(0, 0);
    cp_commit();

    for (int kt = 0; kt < NKT; kt++) {
        int st = kt & 1;
        if (kt + 1 < NKT) load_stage(kt + 1, st ^ 1);
        cp_commit();
        cp_wait1();
        __syncthreads();

        uint32_t bh[4][2], bl[4][2];
#pragma unroll
        for (int np = 0; np < 2; np++) {
            uint32_t r0, r1, r2, r3;
            LDSM4(r0, r1, r2, r3, smem_u32(&sBh[st][(wn + np * 16 + lrow8) * SROW + loff]));
            bh[np*2][0] = r0; bh[np*2+1][0] = r1; bh[np*2][1] = r2; bh[np*2+1][1] = r3;
            LDSM4(r0, r1, r2, r3, smem_u32(&sBm[st][(wn + np * 16 + lrow8) * SROW + loff]));
            bl[np*2][0] = r0; bl[np*2+1][0] = r1; bl[np*2][1] = r2; bl[np*2+1][1] = r3;
        }
#pragma unroll
        for (int mt = 0; mt < MT; mt++) {
            uint32_t ah0, ah1, ah2, ah3, am0, am1, am2, am3;
            LDSM4(ah0, ah1, ah2, ah3, smem_u32(&sAh[st][(wm + mt * 16 + lrow8) * SROW + loff]));
            LDSM4(am0, am1, am2, am3, smem_u32(&sAm[st][(wm + mt * 16 + lrow8) * SROW + loff]));
#pragma unroll
            for (int nt = 0; nt < 4; nt++) {
                MMA_BF16(acc[mt][nt], ah0, ah1, ah2, ah3, bh[nt][0], bh[nt][1]);
                MMA_BF16(acc[mt][nt], ah0, ah1, ah2, ah3, bl[nt][0], bl[nt][1]);
                MMA_BF16(acc[mt][nt], am0, am1, am2, am3, bh[nt][0], bh[nt][1]);
            }
        }
        __syncthreads();
    }

#pragma unroll
    for (int mt = 0; mt < MT; mt++) {
#pragma unroll
        for (int nt = 0; nt < 4; nt++) {
            int row0 = bm0 + wm + mt * 16 + g;
            int col  = bn0 + wn + nt * 8 + t * 2;
            *reinterpret_cast<float2*>(&Co[row0 * N + col]) =
                make_float2(acc[mt][nt][0], acc[mt][nt][1]);
            *reinterpret_cast<float2*>(&Co[(row0 + 8) * N + col]) =
                make_float2(acc[mt][nt][2], acc[mt][nt][3]);
        }
    }
}

__global__ void __launch_bounds__(256, 2) k_gemm_in(void) {
    gemm_body<128, 128, 256, 2>(CC, CIN, g_xh, g_xm, g_wih, g_wim, g_xz);
}
__global__ void __launch_bounds__(128, 4) k_gemm_out(float* __restrict__ Co) {
    gemm_body<64, 128, 128, 1>(CIN, CC, g_ylh, g_ylm, g_woh, g_wom, Co);
}

// ---------------- fused depthwise conv3x3 + SiLU + gather to scan order -----
__global__ void k_convgather(const float* __restrict__ cw, const float* __restrict__ cb) {
    __shared__ float t[32][33];
    int bk = blockIdx.z;
    int b = bk / KG, k = bk % KG;
    int l0 = blockIdx.x * 32;
    int d0 = blockIdx.y * 32;
    int tx = threadIdx.x, ty = threadIdx.y;
    int c = k * DD + d0 + tx;
    float w9[9];
#pragma unroll
    for (int i = 0; i < 9; i++) w9[i] = cw[c * 9 + i];
    float bias = cb[c];
#pragma unroll
    for (int r = 0; r < 4; r++) {
        int lq = l0 + ty + r * 8;
        int lsp = lsp_of(k, lq);
        int h = lsp / WW, w = lsp % WW;
        float acc = bias;
#pragma unroll
        for (int dh = 0; dh < 3; dh++) {
            int hh = h + dh - 1;
            if (hh < 0 || hh >= HH) continue;
#pragma unroll
            for (int dw = 0; dw < 3; dw++) {
                int ww2 = w + dw - 1;
                if (ww2 < 0 || ww2 >= WW) continue;
                acc = fmaf(g_xz[(b * LL + hh * WW + ww2) * CC + c], w9[dh * 3 + dw], acc);
            }
        }
        float sg = 1.f / (1.f + __expf(-acc));
        t[tx][ty + r * 8] = acc * sg;
    }
    __syncthreads();
#pragma unroll
    for (int r = 0; r < 4; r++) {
        int dq = ty + r * 8;
        g_xs[(bk * DD + d0 + dq) * LL + l0 + tx] = t[dq][tx];
    }
}

// ---------------- fused x_proj + dt_proj, d-split for occupancy -------------
__global__ void __launch_bounds__(384) k_xdt(const float* __restrict__ xpw,
                                             const float* __restrict__ dtw,
                                             const float* __restrict__ dtb) {
    __shared__ float pool[CDBL * DD];     // 33 KB: ws in phase A, wd in phase B
    __shared__ float spart[CDBL][64];     // 11 KB
    __shared__ float bd[DD];
    int bk = blockIdx.y;
    int k = bk % KG;
    for (int i = threadIdx.x; i < CDBL * DD; i += 384)
        pool[i] = xpw[k * CDBL * DD + i];
    __syncthreads();

    int grp  = threadIdx.x / 64;          // 0..5
    int li   = threadIdx.x % 64;
    int pair = grp % 3;                   // 0 dts, 1 B, 2 C
    int half = grp / 3;
    int l    = blockIdx.x * 64 + li;
    int nch  = (pair == 0) ? RR : NS;
    int c0   = (pair == 0) ? 0 : (RR + (pair - 1) * NS);
    const float* xp = g_xs + bk * DD * LL + l;
    const float* wp = pool + c0 * DD;
    int dlo = half * 96;

    float acc[NS];
#pragma unroll
    for (int j = 0; j < NS; j++) acc[j] = 0.f;
#pragma unroll 1
    for (int d0 = dlo; d0 < dlo + 96; d0 += 8) {
        float xv[8];
#pragma unroll
        for (int q = 0; q < 8; q++) xv[q] = xp[(d0 + q) * LL];
#pragma unroll
        for (int q = 0; q < 8; q++) {
            if (pair == 0) {
#pragma unroll
                for (int j = 0; j < RR; j++)
                    acc[j] = fmaf(wp[j * DD + d0 + q], xv[q], acc[j]);
            } else {
#pragma unroll
                for (int j = 0; j < NS; j++)
                    acc[j] = fmaf(wp[j * DD + d0 + q], xv[q], acc[j]);
            }
        }
    }

    if (half == 1) {
#pragma unroll
        for (int j = 0; j < NS; j++)
            if (j < nch) spart[c0 + j][li] = acc[j];
    }
    __syncthreads();
    if (half == 0) {
#pragma unroll
        for (int j = 0; j < NS; j++)
            if (j < nch) acc[j] += spart[c0 + j][li];
        if (pair == 0) {
#pragma unroll
            for (int j = 0; j < RR; j++) spart[j][li] = acc[j];
        } else {
            float* ob = ((pair == 1) ? g_B : g_C) + (bk * LL + l) * NS;
#pragma unroll
            for (int j = 0; j < 4; j++) {
                float4 v = make_float4(acc[j*4], acc[j*4+1], acc[j*4+2], acc[j*4+3]);
                *reinterpret_cast<float4*>(&ob[j * 4]) = v;
            }
        }
    }
    __syncthreads();

    for (int i = threadIdx.x; i < DD * RR; i += 384)
        pool[i] = dtw[k * DD * RR + i];
    for (int i = threadIdx.x; i < DD; i += 384)
        bd[i] = dtb[k * DD + i];
    __syncthreads();

    float xr[RR];
#pragma unroll
    for (int r = 0; r < RR; r++) xr[r] = spart[r][li];
    int dbase = grp * 32;
#pragma unroll 4
    for (int dd = 0; dd < 32; dd++) {
        int dch = dbase + dd;
        float a = bd[dch];
#pragma unroll
        for (int r = 0; r < RR; r++) a = fmaf(xr[r], pool[dch * RR + r], a);
        g_dt[(bk * DD + dch) * LL + l] = softplusf(a);
    }
}

// ---------------- fully fused selective scan: one block per bkd -------------
// 256 threads = 8 warps; warp w covers chunks 2w, 2w+1 (lane: g=chunk-in-warp,
// n=state). Pass1 local scan -> smem; in-block prefix over 16 chunks; pass3
// recompute with prefix (L1-hot re-reads) and emit y.
__global__ void __launch_bounds__(256) k_scan(const float* __restrict__ alog,
                                              const float* __restrict__ Ds) {
    __shared__ float sh[NCH][NS];    // hend -> hin (in place)
    __shared__ float sa[NCH][NS];    // aprod
    const int bkd = blockIdx.x;
    const int tid = threadIdx.x;
    const int lane = tid & 31;
    const int g = lane >> 4;
    const int n = lane & 15;
    const int chunk = (tid >> 5) * 2 + g;

    const int b  = bkd / (KG * DD);
    const int kd = bkd % (KG * DD);
    const int k  = kd / DD, dch = kd % DD;
    const int bk = bkd / DD;
    const float An = -__expf(alog[kd * NS + n]);
    const float Dv = Ds[kd];

    const float* dtp = g_dt + bkd * LL + chunk * CHL;
    const float* up  = g_xs + bkd * LL + chunk * CHL;
    const float* bp  = g_B + (bk * LL + chunk * CHL) * NS + n;
    const float* cp  = g_C + (bk * LL + chunk * CHL) * NS + n;

    // pass 1: local scan (h_end, decay product via sum of dt)
    {
        float h = 0.f, s = 0.f;
#pragma unroll 4
        for (int i = 0; i < CHL; i++) {
            float d_ = dtp[i];
            float u_ = up[i];
            float b_ = bp[i * NS];
            s += d_;
            h = fmaf(h, __expf(d_ * An), d_ * u_ * b_);
        }
        sh[chunk][n] = h;
        sa[chunk][n] = __expf(An * s);
    }
    __syncthreads();

    // pass 2: serial prefix across 16 chunks, one thread per n
    if (tid < NS) {
        float hrun = 0.f;
#pragma unroll
        for (int c = 0; c < NCH; c++) {
            float hend = sh[c][tid];
            float ap   = sa[c][tid];
            sh[c][tid] = hrun;                 // overwrite with h_in
            hrun = fmaf(ap, hrun, hend);
        }
    }
    __syncthreads();

    // pass 3: recompute with prefix, reduce over n, emit y
    {
        float h = sh[chunk][n];
        const int cglob = k * DD + dch;
#pragma unroll 2
        for (int i = 0; i < CHL; i++) {
            float d_ = dtp[i];
            float u_ = up[i];
            float b_ = bp[i * NS];
            float c_ = cp[i * NS];
            h = fmaf(h, __expf(d_ * An), d_ * u_ * b_);
            float p = h * c_;
            p += __shfl_xor_sync(0xffffffffu, p, 1);
            p += __shfl_xor_sync(0xffffffffu, p, 2);
            p += __shfl_xor_sync(0xffffffffu, p, 4);
            p += __shfl_xor_sync(0xffffffffu, p, 8);
            if (n == 0) {
                int l = chunk * CHL + i;
                int lsp = lsp_of(k, l);
                g_ym[(b * LL + lsp) * CC + cglob] = fmaf(Dv, u_, p);
            }
        }
    }
}

// ---------------- layernorm over C=768, writes bf16 hi/mid split ------------
__global__ void k_ln(const float* __restrict__ w, const float* __restrict__ bia) {
    int row = blockIdx.x;
    const float* yp = g_ym + row * CC;
    int tid = threadIdx.x;
    float s = 0.f, q = 0.f;
#pragma unroll
    for (int c = tid; c < CC; c += 256) {
        float v = yp[c];
        s += v; q = fmaf(v, v, q);
    }
#pragma unroll
    for (int off = 16; off; off >>= 1) {
        s += __shfl_xor_sync(0xffffffffu, s, off);
        q += __shfl_xor_sync(0xffffffffu, q, off);
    }
    __shared__ float ss[8], qq[8];
    int wid = tid >> 5;
    if ((tid & 31) == 0) { ss[wid] = s; qq[wid] = q; }
    __syncthreads();
    if (tid == 0) {
        float S = 0.f, Q = 0.f;
#pragma unroll
        for (int i = 0; i < 8; i++) { S += ss[i]; Q += qq[i]; }
        float mean = S / (float)CC;
        float var = Q / (float)CC - mean * mean;
        ss[0] = mean;
        qq[0] = rsqrtf(var + 1e-5f);
    }
    __syncthreads();
    float mean = ss[0], rstd = qq[0];
#pragma unroll
    for (int c = tid; c < CC; c += 256) {
        float v = fmaf((yp[c] - mean) * rstd, w[c], bia[c]);
        __nv_bfloat16 h = __float2bfloat16(v);
        g_ylh[row * CC + c] = h;
        g_ylm[row * CC + c] = __float2bfloat16(v - __bfloat162float(h));
    }
}

// ---------------- host launcher ----------------
extern "C" void kernel_launch(void* const* d_in, const int* in_sizes, int n_in,
                              void* d_out, int out_size) {
    const float* x    = (const float*)d_in[0];
    const float* ipw  = (const float*)d_in[1];
    const float* cw   = (const float*)d_in[2];
    const float* cb   = (const float*)d_in[3];
    const float* xpw  = (const float*)d_in[4];
    const float* dtw  = (const float*)d_in[5];
    const float* dtb  = (const float*)d_in[6];
    const float* alog = (const float*)d_in[7];
    const float* Ds   = (const float*)d_in[8];
    const float* nw   = (const float*)d_in[9];
    const float* nb   = (const float*)d_in[10];
    const float* opw  = (const float*)d_in[11];
    float* out = (float*)d_out;

    // 0. fused bf16 split of all GEMM operands
    {
        const int n3 = BL * CIN + CC * CIN + CIN * CC;
        k_split3<<<(n3 + 255) / 256, 256>>>(x, ipw, opw);
    }
    // 1. in_proj GEMM (bf16 3-split, R8 config)
    {
        dim3 grid(CC / 128, BL / 128);
        k_gemm_in<<<grid, 256>>>();
    }
    // 2. fused conv3x3 + SiLU + gather
    {
        dim3 grid(LL / 32, DD / 32, BSZ * KG);
        dim3 blk(32, 8);
        k_convgather<<<grid, blk>>>(cw, cb);
    }
    // 3. fused x_proj + dt_proj (d-split, 384 threads)
    {
        dim3 grid(LL / 64, BSZ * KG);
        k_xdt<<<grid, 384>>>(xpw, dtw, dtb);
    }
    // 4. fully fused selective scan (one block per bkd)
    k_scan<<<NBKD, 256>>>(alog, Ds);
    // 5. layernorm (emits bf16 split)
    k_ln<<<BL, 256>>>(nw, nb);
    // 6. out_proj GEMM (bf16 3-split, R8 config)
    {
        dim3 grid(CIN / 128, BL / 64);
        k_gemm_out<<<grid, 128>>>(out);
    }
}

// round 13
// speedup vs baseline: 1.5000x; 1.5000x over previous
#include <cuda_runtime.h>
#include <cuda_bf16.h>
#include <math.h>
#include <stdint.h>

// ---------------- problem constants ----------------
#define BSZ 2
#define HH  48
#define WW  48
#define LL  (HH*WW)          // 2304
#define CIN 384              // 2*D_MODEL
#define CC  768              // C_INNER
#define KG  4
#define DD  192              // D_IN
#define NS  16
#define RR  12
#define CDBL 44              // R + 2N
#define BL  (BSZ*LL)         // 4608
#define NCH 16
#define CHL (LL/NCH)         // 144
#define NBKD (BSZ*KG*DD)     // 1536

// ---------------- device scratch ----------------
__device__ float g_xz  [BL*CC];          // in_proj output, [B*L, 768] channel-last
__device__ float g_xs  [BSZ*KG*DD*LL];   // scan inputs u, [bkd][L]
__device__ float g_B   [BSZ*KG*LL*NS];   // B, [bk][l][n]  (n fastest)
__device__ float g_C   [BSZ*KG*LL*NS];   // C, [bk][l][n]
__device__ float g_dt  [BSZ*KG*DD*LL];   // softplus(dt), [bkd][L]
__device__ float g_hend [NBKD*NCH*NS];
__device__ float g_aprod[NBKD*NCH*NS];
__device__ float g_hin  [NBKD*NCH*NS];
__device__ float g_ym  [BL*CC];          // y merged spatially, [B*L, 768]

// bf16 split operand buffers for tensor-core GEMMs
__device__ __nv_bfloat16 g_xh [BL*CIN],  g_xm [BL*CIN];   // x split
__device__ __nv_bfloat16 g_wih[CC*CIN],  g_wim[CC*CIN];   // in_proj_w split
__device__ __nv_bfloat16 g_woh[CIN*CC],  g_wom[CIN*CC];   // out_proj_w split
__device__ __nv_bfloat16 g_ylh[BL*CC],   g_ylm[BL*CC];    // layernorm output split

// scan-order index -> spatial index, per direction k
__device__ __forceinline__ int lsp_of(int k, int l) {
    switch (k) {
        case 0:  return l;
        case 1:  return (l % HH) * WW + (l / HH);
        case 2:  return LL - 1 - l;
        default: { int l2 = LL - 1 - l; return (l2 % HH) * WW + (l2 / HH); }
    }
}

__device__ __forceinline__ float softplusf(float x) {
    return (x > 15.f) ? x : log1pf(__expf(x));
}

__device__ __forceinline__ uint32_t smem_u32(const void* p) {
    return (uint32_t)__cvta_generic_to_shared(p);
}

__device__ __forceinline__ void cp16(uint32_t saddr, const void* g) {
    asm volatile("cp.async.cg.shared.global [%0], [%1], 16;" :: "r"(saddr), "l"(g));
}
__device__ __forceinline__ void cp_commit() {
    asm volatile("cp.async.commit_group;");
}
__device__ __forceinline__ void cp_wait1() {
    asm volatile("cp.async.wait_group 1;");
}

// ---------------- fused bf16 split (x, in_proj_w, out_proj_w) ---------------
__global__ void k_split3(const float* __restrict__ x,
                         const float* __restrict__ ipw,
                         const float* __restrict__ opw) {
    const int n1 = BL * CIN, n2 = n1 + CC * CIN, n3 = n2 + CIN * CC;
    int i = blockIdx.x * blockDim.x + threadIdx.x;
    if (i >= n3) return;
    const float* s; __nv_bfloat16 *hp, *mp; int off;
    if (i < n1)      { s = x;   hp = g_xh;  mp = g_xm;  off = i; }
    else if (i < n2) { s = ipw; hp = g_wih; mp = g_wim; off = i - n1; }
    else             { s = opw; hp = g_woh; mp = g_wom; off = i - n2; }
    float v = s[off];
    __nv_bfloat16 h = __float2bfloat16(v);
    hp[off] = h;
    mp[off] = __float2bfloat16(v - __bfloat162float(h));
}

// ---------------- bf16 3-split tensor-core GEMM (NT) ------------------------
// R8 measured-best config. C[M,N]=A*B^T via Ah*Bh + Ah*Bm + Am*Bh, fp32 accum.
// Warp tile 64x32 (MT=4 x NT=4), ldmatrix frags, cp.async 2-stage pipeline.

#define SROW 12   // smem row stride in words (8 data + 4 pad)

#define MMA_BF16(C, a0,a1,a2,a3, b0,b1) \
    asm volatile("mma.sync.aligned.m16n8k16.row.col.f32.bf16.bf16.f32 " \
        "{%0,%1,%2,%3},{%4,%5,%6,%7},{%8,%9},{%0,%1,%2,%3};" \
        : "+f"(C[0]), "+f"(C[1]), "+f"(C[2]), "+f"(C[3]) \
        : "r"(a0), "r"(a1), "r"(a2), "r"(a3), "r"(b0), "r"(b1))

#define LDSM4(r0,r1,r2,r3,addr) \
    asm volatile("ldmatrix.sync.aligned.m8n8.x4.shared.b16 {%0,%1,%2,%3}, [%4];" \
        : "=r"(r0), "=r"(r1), "=r"(r2), "=r"(r3) : "r"(addr))

template<int BM, int BN, int NTHR, int WR>
__device__ __forceinline__ void gemm_body(int N, int Kd,
        const __nv_bfloat16* __restrict__ Ahp, const __nv_bfloat16* __restrict__ Amp,
        const __nv_bfloat16* __restrict__ Bhp, const __nv_bfloat16* __restrict__ Bmp,
        float* __restrict__ Co) {
    constexpr int MT = BM / (WR * 16);      // 4
    __shared__ uint32_t sAh[2][BM * SROW], sAm[2][BM * SROW];
    __shared__ uint32_t sBh[2][BN * SROW], sBm[2][BN * SROW];

    const int tid  = threadIdx.x;
    const int lane = tid & 31;
    const int wid  = tid >> 5;
    const int g    = lane >> 2;
    const int t    = lane & 3;
    const int wm   = (wid % WR) * (MT * 16);
    const int wn   = (wid / WR) * 32;
    const int bm0  = blockIdx.y * BM;
    const int bn0  = blockIdx.x * BN;
    const int Kw   = Kd >> 1;

    const uint32_t* gAh = (const uint32_t*)Ahp;
    const uint32_t* gAm = (const uint32_t*)Amp;
    const uint32_t* gBh = (const uint32_t*)Bhp;
    const uint32_t* gBm = (const uint32_t*)Bmp;

    const int lrow8 = ((lane >> 3) & 1) * 8 + (lane & 7);
    const int loff  = (lane >> 4) * 4;

    float acc[MT][4][4];
#pragma unroll
    for (int mt = 0; mt < MT; mt++)
#pragma unroll
        for (int nt = 0; nt < 4; nt++)
#pragma unroll
            for (int j = 0; j < 4; j++) acc[mt][nt][j] = 0.f;

    auto load_stage = [&](int kt, int st) {
        const int k0w = kt * 8;
#pragma unroll
        for (int idx = tid; idx < 2 * (BM + BN); idx += NTHR) {
            int half = idx & 1, r = idx >> 1;
            if (r < BM) {
                cp16(smem_u32(&sAh[st][r * SROW + half * 4]),
                     &gAh[(bm0 + r) * Kw + k0w + half * 4]);
                cp16(smem_u32(&sAm[st][r * SROW + half * 4]),
                     &gAm[(bm0 + r) * Kw + k0w + half * 4]);
            } else {
                int rb = r - BM;
                cp16(smem_u32(&sBh[st][rb * SROW + half * 4]),
                     &gBh[(bn0 + rb) * Kw + k0w + half * 4]);
                cp16(smem_u32(&sBm[st][rb * SROW + half * 4]),
                     &gBm[(bn0 + rb) * Kw + k0w + half * 4]);
            }
        }
    };

    const int NKT = Kw / 8;
    load_stage(0, 0);
    cp_commit();

    for (int kt = 0; kt < NKT; kt++) {
        int st = kt & 1;
        if (kt + 1 < NKT) load_stage(kt + 1, st ^ 1);
        cp_commit();
        cp_wait1();
        __syncthreads();

        uint32_t bh[4][2], bl[4][2];
#pragma unroll
        for (int np = 0; np < 2; np++) {
            uint32_t r0, r1, r2, r3;
            LDSM4(r0, r1, r2, r3, smem_u32(&sBh[st][(wn + np * 16 + lrow8) * SROW + loff]));
            bh[np*2][0] = r0; bh[np*2+1][0] = r1; bh[np*2][1] = r2; bh[np*2+1][1] = r3;
            LDSM4(r0, r1, r2, r3, smem_u32(&sBm[st][(wn + np * 16 + lrow8) * SROW + loff]));
            bl[np*2][0] = r0; bl[np*2+1][0] = r1; bl[np*2][1] = r2; bl[np*2+1][1] = r3;
        }
#pragma unroll
        for (int mt = 0; mt < MT; mt++) {
            uint32_t ah0, ah1, ah2, ah3, am0, am1, am2, am3;
            LDSM4(ah0, ah1, ah2, ah3, smem_u32(&sAh[st][(wm + mt * 16 + lrow8) * SROW + loff]));
            LDSM4(am0, am1, am2, am3, smem_u32(&sAm[st][(wm + mt * 16 + lrow8) * SROW + loff]));
#pragma unroll
            for (int nt = 0; nt < 4; nt++) {
                MMA_BF16(acc[mt][nt], ah0, ah1, ah2, ah3, bh[nt][0], bh[nt][1]);
                MMA_BF16(acc[mt][nt], ah0, ah1, ah2, ah3, bl[nt][0], bl[nt][1]);
                MMA_BF16(acc[mt][nt], am0, am1, am2, am3, bh[nt][0], bh[nt][1]);
            }
        }
        __syncthreads();
    }

#pragma unroll
    for (int mt = 0; mt < MT; mt++) {
#pragma unroll
        for (int nt = 0; nt < 4; nt++) {
            int row0 = bm0 + wm + mt * 16 + g;
            int col  = bn0 + wn + nt * 8 + t * 2;
            *reinterpret_cast<float2*>(&Co[row0 * N + col]) =
                make_float2(acc[mt][nt][0], acc[mt][nt][1]);
            *reinterpret_cast<float2*>(&Co[(row0 + 8) * N + col]) =
                make_float2(acc[mt][nt][2], acc[mt][nt][3]);
        }
    }
}

__global__ void __launch_bounds__(256, 2) k_gemm_in(void) {
    gemm_body<128, 128, 256, 2>(CC, CIN, g_xh, g_xm, g_wih, g_wim, g_xz);
}
__global__ void __launch_bounds__(128, 4) k_gemm_out(float* __restrict__ Co) {
    gemm_body<64, 128, 128, 1>(CIN, CC, g_ylh, g_ylm, g_woh, g_wom, Co);
}

// ---------------- fused depthwise conv3x3 + SiLU + gather to scan order -----
__global__ void k_convgather(const float* __restrict__ cw, const float* __restrict__ cb) {
    __shared__ float t[32][33];
    int bk = blockIdx.z;
    int b = bk / KG, k = bk % KG;
    int l0 = blockIdx.x * 32;
    int d0 = blockIdx.y * 32;
    int tx = threadIdx.x, ty = threadIdx.y;
    int c = k * DD + d0 + tx;
    float w9[9];
#pragma unroll
    for (int i = 0; i < 9; i++) w9[i] = cw[c * 9 + i];
    float bias = cb[c];
#pragma unroll
    for (int r = 0; r < 4; r++) {
        int lq = l0 + ty + r * 8;
        int lsp = lsp_of(k, lq);
        int h = lsp / WW, w = lsp % WW;
        float acc = bias;
#pragma unroll
        for (int dh = 0; dh < 3; dh++) {
            int hh = h + dh - 1;
            if (hh < 0 || hh >= HH) continue;
#pragma unroll
            for (int dw = 0; dw < 3; dw++) {
                int ww2 = w + dw - 1;
                if (ww2 < 0 || ww2 >= WW) continue;
                acc = fmaf(g_xz[(b * LL + hh * WW + ww2) * CC + c], w9[dh * 3 + dw], acc);
            }
        }
        float sg = 1.f / (1.f + __expf(-acc));
        t[tx][ty + r * 8] = acc * sg;
    }
    __syncthreads();
#pragma unroll
    for (int r = 0; r < 4; r++) {
        int dq = ty + r * 8;
        g_xs[(bk * DD + d0 + dq) * LL + l0 + tx] = t[dq][tx];
    }
}

// ---------------- fused x_proj + dt_proj (R8 192-thread version) ------------
__global__ void __launch_bounds__(192) k_xdt(const float* __restrict__ xpw,
                                             const float* __restrict__ dtw,
                                             const float* __restrict__ dtb) {
    __shared__ float ws[CDBL * DD];      // 33 KB
    __shared__ float wd[DD * RR];        // 9 KB
    __shared__ float bd[DD];
    __shared__ float sdtr[64][13];
    int bk = blockIdx.y;
    int k = bk % KG;
    for (int i = threadIdx.x; i < CDBL * DD; i += 192)
        ws[i] = xpw[k * CDBL * DD + i];
    for (int i = threadIdx.x; i < DD * RR; i += 192)
        wd[i] = dtw[k * DD * RR + i];
    for (int i = threadIdx.x; i < DD; i += 192)
        bd[i] = dtb[k * DD + i];
    __syncthreads();

    int grp = threadIdx.x / 64;
    int li  = threadIdx.x % 64;
    int l   = blockIdx.x * 64 + li;
    const float* xp = g_xs + bk * DD * LL + l;

    if (grp == 0) {
        float acc[RR];
#pragma unroll
        for (int j = 0; j < RR; j++) acc[j] = 0.f;
#pragma unroll 1
        for (int d0 = 0; d0 < DD; d0 += 8) {
            float xv[8];
#pragma unroll
            for (int q = 0; q < 8; q++) xv[q] = xp[(d0 + q) * LL];
#pragma unroll
            for (int q = 0; q < 8; q++)
#pragma unroll
                for (int j = 0; j < RR; j++)
                    acc[j] = fmaf(ws[j * DD + d0 + q], xv[q], acc[j]);
        }
#pragma unroll
        for (int j = 0; j < RR; j++) sdtr[li][j] = acc[j];
    } else {
        float acc[NS];
#pragma unroll
        for (int j = 0; j < NS; j++) acc[j] = 0.f;
        const float* wp = ws + (RR + (grp - 1) * NS) * DD;
#pragma unroll 1
        for (int d0 = 0; d0 < DD; d0 += 8) {
            float xv[8];
#pragma unroll
            for (int q = 0; q < 8; q++) xv[q] = xp[(d0 + q) * LL];
#pragma unroll
            for (int q = 0; q < 8; q++)
#pragma unroll
                for (int j = 0; j < NS; j++)
                    acc[j] = fmaf(wp[j * DD + d0 + q], xv[q], acc[j]);
        }
        float* ob = ((grp == 1) ? g_B : g_C) + (bk * LL + l) * NS;
#pragma unroll
        for (int j = 0; j < 4; j++) {
            float4 v = make_float4(acc[j*4], acc[j*4+1], acc[j*4+2], acc[j*4+3]);
            *reinterpret_cast<float4*>(&ob[j * 4]) = v;
        }
    }
    __syncthreads();

    float xr[RR];
#pragma unroll
    for (int r = 0; r < RR; r++) xr[r] = sdtr[li][r];
    int dbase = grp * 64;
#pragma unroll 4
    for (int dd = 0; dd < 64; dd++) {
        int dch = dbase + dd;
        float acc = bd[dch];
#pragma unroll
        for (int r = 0; r < RR; r++) acc = fmaf(xr[r], wd[dch * RR + r], acc);
        g_dt[(bk * DD + dch) * LL + l] = softplusf(acc);
    }
}

// ---------------- scan pass 1: per (bkd, n, chunk) local scan ----------------
__global__ void __launch_bounds__(128) k_scan1(const float* __restrict__ alog) {
    int gid = blockIdx.x * blockDim.x + threadIdx.x;
    int n = gid & 15;
    int unit = gid >> 4;
    int chunk = unit & (NCH - 1);
    int bkd = unit >> 4;
    int kd = bkd % (KG * DD);
    float An = -__expf(alog[kd * NS + n]);
    const float* dtp = g_dt + bkd * LL + chunk * CHL;
    const float* up  = g_xs + bkd * LL + chunk * CHL;
    int bk = bkd / DD;
    const float* bp = g_B + (bk * LL + chunk * CHL) * NS + n;
    float h = 0.f, s = 0.f;
#pragma unroll 8
    for (int i = 0; i < CHL; i++) {
        float d_ = dtp[i];
        float u_ = up[i];
        float b_ = bp[i * NS];
        s += d_;
        h = fmaf(h, __expf(d_ * An), d_ * u_ * b_);
    }
    g_hend[gid]  = h;
    g_aprod[gid] = __expf(An * s);
}

// ---------------- scan pass 2: prefix across chunks ----------------
__global__ void k_scan2(void) {
    int t = blockIdx.x * blockDim.x + threadIdx.x;
    int n = t & 15;
    int bkd = t >> 4;
    int base = bkd * (NCH * NS) + n;
    float h = 0.f;
#pragma unroll
    for (int c = 0; c < NCH; c++) {
        g_hin[base + c * NS] = h;
        h = fmaf(g_aprod[base + c * NS], h, g_hend[base + c * NS]);
    }
}

// ---------------- scan pass 3: recompute with prefix, emit y ----------------
__global__ void k_scan3(const float* __restrict__ alog, const float* __restrict__ Ds) {
    int warp_g = blockIdx.x * (blockDim.x / 32) + (threadIdx.x >> 5);
    int lane = threadIdx.x & 31;
    int g = lane >> 4;
    int n = lane & 15;
    int unit = warp_g * 2 + g;
    int chunk = unit & (NCH - 1);
    int bkd = unit >> 4;
    int b = bkd / (KG * DD);
    int kd = bkd % (KG * DD);
    int k = kd / DD, dch = kd % DD;
    float An = -__expf(alog[kd * NS + n]);
    float Dv = Ds[kd];
    float h = g_hin[unit * NS + n];
    const float* dtp = g_dt + bkd * LL + chunk * CHL;
    const float* up  = g_xs + bkd * LL + chunk * CHL;
    int bk = bkd / DD;
    const float* bp = g_B + (bk * LL + chunk * CHL) * NS + n;
    const float* cp = g_C + (bk * LL + chunk * CHL) * NS + n;
    int cglob = k * DD + dch;
#pragma unroll 4
    for (int i = 0; i < CHL; i++) {
        float d_ = dtp[i];
        float u_ = up[i];
        float b_ = bp[i * NS];
        float c_ = cp[i * NS];
        h = fmaf(h, __expf(d_ * An), d_ * u_ * b_);
        float p = h * c_;
        p += __shfl_xor_sync(0xffffffffu, p, 1);
        p += __shfl_xor_sync(0xffffffffu, p, 2);
        p += __shfl_xor_sync(0xffffffffu, p, 4);
        p += __shfl_xor_sync(0xffffffffu, p, 8);
        if (n == 0) {
            int l = chunk * CHL + i;
            int lsp = lsp_of(k, l);
            g_ym[(b * LL + lsp) * CC + cglob] = fmaf(Dv, u_, p);
        }
    }
}

// ---------------- layernorm over C=768, writes bf16 hi/mid split ------------
__global__ void k_ln(const float* __restrict__ w, const float* __restrict__ bia) {
    int row = blockIdx.x;
    const float* yp = g_ym + row * CC;
    int tid = threadIdx.x;
    float s = 0.f, q = 0.f;
#pragma unroll
    for (int c = tid; c < CC; c += 256) {
        float v = yp[c];
        s += v; q = fmaf(v, v, q);
    }
#pragma unroll
    for (int off = 16; off; off >>= 1) {
        s += __shfl_xor_sync(0xffffffffu, s, off);
        q += __shfl_xor_sync(0xffffffffu, q, off);
    }
    __shared__ float ss[8], qq[8];
    int wid = tid >> 5;
    if ((tid & 31) == 0) { ss[wid] = s; qq[wid] = q; }
    __syncthreads();
    if (tid == 0) {
        float S = 0.f, Q = 0.f;
#pragma unroll
        for (int i = 0; i < 8; i++) { S += ss[i]; Q += qq[i]; }
        float mean = S / (float)CC;
        float var = Q / (float)CC - mean * mean;
        ss[0] = mean;
        qq[0] = rsqrtf(var + 1e-5f);
    }
    __syncthreads();
    float mean = ss[0], rstd = qq[0];
#pragma unroll
    for (int c = tid; c < CC; c += 256) {
        float v = fmaf((yp[c] - mean) * rstd, w[c], bia[c]);
        __nv_bfloat16 h = __float2bfloat16(v);
        g_ylh[row * CC + c] = h;
        g_ylm[row * CC + c] = __float2bfloat16(v - __bfloat162float(h));
    }
}

// ---------------- host launcher ----------------
extern "C" void kernel_launch(void* const* d_in, const int* in_sizes, int n_in,
                              void* d_out, int out_size) {
    const float* x    = (const float*)d_in[0];
    const float* ipw  = (const float*)d_in[1];
    const float* cw   = (const float*)d_in[2];
    const float* cb   = (const float*)d_in[3];
    const float* xpw  = (const float*)d_in[4];
    const float* dtw  = (const float*)d_in[5];
    const float* dtb  = (const float*)d_in[6];
    const float* alog = (const float*)d_in[7];
    const float* Ds   = (const float*)d_in[8];
    const float* nw   = (const float*)d_in[9];
    const float* nb   = (const float*)d_in[10];
    const float* opw  = (const float*)d_in[11];
    float* out = (float*)d_out;

    // 0. fused bf16 split of all GEMM operands
    {
        const int n3 = BL * CIN + CC * CIN + CIN * CC;
        k_split3<<<(n3 + 255) / 256, 256>>>(x, ipw, opw);
    }
    // 1. in_proj GEMM (bf16 3-split, R8 config)
    {
        dim3 grid(CC / 128, BL / 128);
        k_gemm_in<<<grid, 256>>>();
    }
    // 2. fused conv3x3 + SiLU + gather
    {
        dim3 grid(LL / 32, DD / 32, BSZ * KG);
        dim3 blk(32, 8);
        k_convgather<<<grid, blk>>>(cw, cb);
    }
    // 3. fused x_proj + dt_proj
    {
        dim3 grid(LL / 64, BSZ * KG);
        k_xdt<<<grid, 192>>>(xpw, dtw, dtb);
    }
    // 4-6. chunked selective scan
    k_scan1<<<(NBKD * NCH * NS) / 128, 128>>>(alog);
    k_scan2<<<(NBKD * NS) / 128, 128>>>();
    k_scan3<<<(NBKD * NCH) / 2 / 8, 256>>>(alog, Ds);
    // 7. layernorm (emits bf16 split)
    k_ln<<<BL, 256>>>(nw, nb);
    // 8. out_proj GEMM (bf16 3-split, R8 config)
    {
        dim3 grid(CIN / 128, BL / 64);
        k_gemm_out<<<grid, 128>>>(out);
    }
}

// round 14
// speedup vs baseline: 1.5278x; 1.0185x over previous
#include <cuda_runtime.h>
#include <cuda_bf16.h>
#include <math.h>
#include <stdint.h>

// ---------------- problem constants ----------------
#define BSZ 2
#define HH  48
#define WW  48
#define LL  (HH*WW)          // 2304
#define CIN 384              // 2*D_MODEL
#define CC  768              // C_INNER
#define KG  4
#define DD  192              // D_IN
#define NS  16
#define RR  12
#define CDBL 44              // R + 2N
#define BL  (BSZ*LL)         // 4608
#define NCH 16
#define CHL (LL/NCH)         // 144
#define NBKD (BSZ*KG*DD)     // 1536

// ---------------- device scratch ----------------
__device__ float g_xz  [BL*CC];          // in_proj output, [B*L, 768] channel-last
__device__ float g_xs  [BSZ*KG*DD*LL];   // scan inputs u, [bkd][L]
__device__ float g_B   [BSZ*KG*LL*NS];   // B, [bk][l][n]  (n fastest)
__device__ float g_C   [BSZ*KG*LL*NS];   // C, [bk][l][n]
__device__ float g_dt  [BSZ*KG*DD*LL];   // softplus(dt), [bkd][L]
__device__ float g_hend [NBKD*NCH*NS];
__device__ float g_aprod[NBKD*NCH*NS];
__device__ float g_hin  [NBKD*NCH*NS];
__device__ float g_ym  [BL*CC];          // y merged spatially, [B*L, 768]

// bf16 split operand buffers for tensor-core GEMMs
__device__ __nv_bfloat16 g_xh [BL*CIN],  g_xm [BL*CIN];   // x split
__device__ __nv_bfloat16 g_wih[CC*CIN],  g_wim[CC*CIN];   // in_proj_w split
__device__ __nv_bfloat16 g_woh[CIN*CC],  g_wom[CIN*CC];   // out_proj_w split
__device__ __nv_bfloat16 g_ylh[BL*CC],   g_ylm[BL*CC];    // layernorm output split

// scan-order index -> spatial index, per direction k
__device__ __forceinline__ int lsp_of(int k, int l) {
    switch (k) {
        case 0:  return l;
        case 1:  return (l % HH) * WW + (l / HH);
        case 2:  return LL - 1 - l;
        default: { int l2 = LL - 1 - l; return (l2 % HH) * WW + (l2 / HH); }
    }
}

__device__ __forceinline__ float softplusf(float x) {
    return (x > 15.f) ? x : log1pf(__expf(x));
}

__device__ __forceinline__ uint32_t smem_u32(const void* p) {
    return (uint32_t)__cvta_generic_to_shared(p);
}

__device__ __forceinline__ void cp16(uint32_t saddr, const void* g) {
    asm volatile("cp.async.cg.shared.global [%0], [%1], 16;" :: "r"(saddr), "l"(g));
}
__device__ __forceinline__ void cp_commit() {
    asm volatile("cp.async.commit_group;");
}
__device__ __forceinline__ void cp_wait1() {
    asm volatile("cp.async.wait_group 1;");
}

// ---------------- fused bf16 split, float4 vectorized ----------------------
// n3/4 threads, each handles 4 consecutive floats -> 2 packed bf16x2 stores.
__global__ void k_split3(const float* __restrict__ x,
                         const float* __restrict__ ipw,
                         const float* __restrict__ opw) {
    const int q1 = (BL * CIN) / 4, q2 = q1 + (CC * CIN) / 4, q3 = q2 + (CIN * CC) / 4;
    int i = blockIdx.x * blockDim.x + threadIdx.x;
    if (i >= q3) return;
    const float* s; __nv_bfloat16 *hp, *mp; int off;
    if (i < q1)      { s = x;   hp = g_xh;  mp = g_xm;  off = i; }
    else if (i < q2) { s = ipw; hp = g_wih; mp = g_wim; off = i - q1; }
    else             { s = opw; hp = g_woh; mp = g_wom; off = i - q2; }
    float4 v = reinterpret_cast<const float4*>(s)[off];
    float vv[4] = {v.x, v.y, v.z, v.w};
    __nv_bfloat16 h4[4], m4[4];
#pragma unroll
    for (int j = 0; j < 4; j++) {
        h4[j] = __float2bfloat16(vv[j]);
        m4[j] = __float2bfloat16(vv[j] - __bfloat162float(h4[j]));
    }
    reinterpret_cast<uint2*>(hp)[off] = *reinterpret_cast<uint2*>(h4);
    reinterpret_cast<uint2*>(mp)[off] = *reinterpret_cast<uint2*>(m4);
}

// ---------------- bf16 3-split tensor-core GEMM (NT) ------------------------
// R8 measured-best config. C[M,N]=A*B^T via Ah*Bh + Ah*Bm + Am*Bh, fp32 accum.
// Warp tile 64x32 (MT=4 x NT=4), ldmatrix frags, cp.async 2-stage pipeline.

#define SROW 12   // smem row stride in words (8 data + 4 pad)

#define MMA_BF16(C, a0,a1,a2,a3, b0,b1) \
    asm volatile("mma.sync.aligned.m16n8k16.row.col.f32.bf16.bf16.f32 " \
        "{%0,%1,%2,%3},{%4,%5,%6,%7},{%8,%9},{%0,%1,%2,%3};" \
        : "+f"(C[0]), "+f"(C[1]), "+f"(C[2]), "+f"(C[3]) \
        : "r"(a0), "r"(a1), "r"(a2), "r"(a3), "r"(b0), "r"(b1))

#define LDSM4(r0,r1,r2,r3,addr) \
    asm volatile("ldmatrix.sync.aligned.m8n8.x4.shared.b16 {%0,%1,%2,%3}, [%4];" \
        : "=r"(r0), "=r"(r1), "=r"(r2), "=r"(r3) : "r"(addr))

template<int BM, int BN, int NTHR, int WR>
__device__ __forceinline__ void gemm_body(int N, int Kd,
        const __nv_bfloat16* __restrict__ Ahp, const __nv_bfloat16* __restrict__ Amp,
        const __nv_bfloat16* __restrict__ Bhp, const __nv_bfloat16* __restrict__ Bmp,
        float* __restrict__ Co) {
    constexpr int MT = BM / (WR * 16);      // 4
    __shared__ uint32_t sAh[2][BM * SROW], sAm[2][BM * SROW];
    __shared__ uint32_t sBh[2][BN * SROW], sBm[2][BN * SROW];

    const int tid  = threadIdx.x;
    const int lane = tid & 31;
    const int wid  = tid >> 5;
    const int g    = lane >> 2;
    const int t    = lane & 3;
    const int wm   = (wid % WR) * (MT * 16);
    const int wn   = (wid / WR) * 32;
    const int bm0  = blockIdx.y * BM;
    const int bn0  = blockIdx.x * BN;
    const int Kw   = Kd >> 1;

    const uint32_t* gAh = (const uint32_t*)Ahp;
    const uint32_t* gAm = (const uint32_t*)Amp;
    const uint32_t* gBh = (const uint32_t*)Bhp;
    const uint32_t* gBm = (const uint32_t*)Bmp;

    const int lrow8 = ((lane >> 3) & 1) * 8 + (lane & 7);
    const int loff  = (lane >> 4) * 4;

    float acc[MT][4][4];
#pragma unroll
    for (int mt = 0; mt < MT; mt++)
#pragma unroll
        for (int nt = 0; nt < 4; nt++)
#pragma unroll
            for (int j = 0; j < 4; j++) acc[mt][nt][j] = 0.f;

    auto load_stage = [&](int kt, int st) {
        const int k0w = kt * 8;
#pragma unroll
        for (int idx = tid; idx < 2 * (BM + BN); idx += NTHR) {
            int half = idx & 1, r = idx >> 1;
            if (r < BM) {
                cp16(smem_u32(&sAh[st][r * SROW + half * 4]),
                     &gAh[(bm0 + r) * Kw + k0w + half * 4]);
                cp16(smem_u32(&sAm[st][r * SROW + half * 4]),
                     &gAm[(bm0 + r) * Kw + k0w + half * 4]);
            } else {
                int rb = r - BM;
                cp16(smem_u32(&sBh[st][rb * SROW + half * 4]),
                     &gBh[(bn0 + rb) * Kw + k0w + half * 4]);
                cp16(smem_u32(&sBm[st][rb * SROW + half * 4]),
                     &gBm[(bn0 + rb) * Kw + k0w + half * 4]);
            }
        }
    };

    const int NKT = Kw / 8;
    load_stage(0, 0);
    cp_commit();

    for (int kt = 0; kt < NKT; kt++) {
        int st = kt & 1;
        if (kt + 1 < NKT) load_stage(kt + 1, st ^ 1);
        cp_commit();
        cp_wait1();
        __syncthreads();

        uint32_t bh[4][2], bl[4][2];
#pragma unroll
        for (int np = 0; np < 2; np++) {
            uint32_t r0, r1, r2, r3;
            LDSM4(r0, r1, r2, r3, smem_u32(&sBh[st][(wn + np * 16 + lrow8) * SROW + loff]));
            bh[np*2][0] = r0; bh[np*2+1][0] = r1; bh[np*2][1] = r2; bh[np*2+1][1] = r3;
            LDSM4(r0, r1, r2, r3, smem_u32(&sBm[st][(wn + np * 16 + lrow8) * SROW + loff]));
            bl[np*2][0] = r0; bl[np*2+1][0] = r1; bl[np*2][1] = r2; bl[np*2+1][1] = r3;
        }
#pragma unroll
        for (int mt = 0; mt < MT; mt++) {
            uint32_t ah0, ah1, ah2, ah3, am0, am1, am2, am3;
            LDSM4(ah0, ah1, ah2, ah3, smem_u32(&sAh[st][(wm + mt * 16 + lrow8) * SROW + loff]));
            LDSM4(am0, am1, am2, am3, smem_u32(&sAm[st][(wm + mt * 16 + lrow8) * SROW + loff]));
#pragma unroll
            for (int nt = 0; nt < 4; nt++) {
                MMA_BF16(acc[mt][nt], ah0, ah1, ah2, ah3, bh[nt][0], bh[nt][1]);
                MMA_BF16(acc[mt][nt], ah0, ah1, ah2, ah3, bl[nt][0], bl[nt][1]);
                MMA_BF16(acc[mt][nt], am0, am1, am2, am3, bh[nt][0], bh[nt][1]);
            }
        }
        __syncthreads();
    }

#pragma unroll
    for (int mt = 0; mt < MT; mt++) {
#pragma unroll
        for (int nt = 0; nt < 4; nt++) {
            int row0 = bm0 + wm + mt * 16 + g;
            int col  = bn0 + wn + nt * 8 + t * 2;
            *reinterpret_cast<float2*>(&Co[row0 * N + col]) =
                make_float2(acc[mt][nt][0], acc[mt][nt][1]);
            *reinterpret_cast<float2*>(&Co[(row0 + 8) * N + col]) =
                make_float2(acc[mt][nt][2], acc[mt][nt][3]);
        }
    }
}

__global__ void __launch_bounds__(256, 2) k_gemm_in(void) {
    gemm_body<128, 128, 256, 2>(CC, CIN, g_xh, g_xm, g_wih, g_wim, g_xz);
}
__global__ void __launch_bounds__(128, 4) k_gemm_out(float* __restrict__ Co) {
    gemm_body<64, 128, 128, 1>(CIN, CC, g_ylh, g_ylm, g_woh, g_wom, Co);
}

// ---------------- fused depthwise conv3x3 + SiLU + gather to scan order -----
__global__ void k_convgather(const float* __restrict__ cw, const float* __restrict__ cb) {
    __shared__ float t[32][33];
    int bk = blockIdx.z;
    int b = bk / KG, k = bk % KG;
    int l0 = blockIdx.x * 32;
    int d0 = blockIdx.y * 32;
    int tx = threadIdx.x, ty = threadIdx.y;
    int c = k * DD + d0 + tx;
    float w9[9];
#pragma unroll
    for (int i = 0; i < 9; i++) w9[i] = cw[c * 9 + i];
    float bias = cb[c];
#pragma unroll
    for (int r = 0; r < 4; r++) {
        int lq = l0 + ty + r * 8;
        int lsp = lsp_of(k, lq);
        int h = lsp / WW, w = lsp % WW;
        float acc = bias;
#pragma unroll
        for (int dh = 0; dh < 3; dh++) {
            int hh = h + dh - 1;
            if (hh < 0 || hh >= HH) continue;
#pragma unroll
            for (int dw = 0; dw < 3; dw++) {
                int ww2 = w + dw - 1;
                if (ww2 < 0 || ww2 >= WW) continue;
                acc = fmaf(g_xz[(b * LL + hh * WW + ww2) * CC + c], w9[dh * 3 + dw], acc);
            }
        }
        float sg = 1.f / (1.f + __expf(-acc));
        t[tx][ty + r * 8] = acc * sg;
    }
    __syncthreads();
#pragma unroll
    for (int r = 0; r < 4; r++) {
        int dq = ty + r * 8;
        g_xs[(bk * DD + d0 + dq) * LL + l0 + tx] = t[dq][tx];
    }
}

// ---------------- fused x_proj + dt_proj, d-split (R9 measured-best) --------
// 384 threads = 6 half-groups: pair = grp%3 (0=dts,1=B,2=C), half = grp/3
// (d 0-95 vs 96-191), 64 l each. High half writes partials to smem; low half
// combines + writes outputs. Phase B: dt-proj over 6 x 32 dch slices.
__global__ void __launch_bounds__(384) k_xdt(const float* __restrict__ xpw,
                                             const float* __restrict__ dtw,
                                             const float* __restrict__ dtb) {
    __shared__ float pool[CDBL * DD];     // 33 KB: ws in phase A, wd in phase B
    __shared__ float spart[CDBL][64];     // 11 KB
    __shared__ float bd[DD];
    int bk = blockIdx.y;
    int k = bk % KG;
    for (int i = threadIdx.x; i < CDBL * DD; i += 384)
        pool[i] = xpw[k * CDBL * DD + i];
    __syncthreads();

    int grp  = threadIdx.x / 64;          // 0..5
    int li   = threadIdx.x % 64;
    int pair = grp % 3;                   // 0 dts, 1 B, 2 C
    int half = grp / 3;
    int l    = blockIdx.x * 64 + li;
    int nch  = (pair == 0) ? RR : NS;
    int c0   = (pair == 0) ? 0 : (RR + (pair - 1) * NS);
    const float* xp = g_xs + bk * DD * LL + l;
    const float* wp = pool + c0 * DD;
    int dlo = half * 96;

    float acc[NS];
#pragma unroll
    for (int j = 0; j < NS; j++) acc[j] = 0.f;
#pragma unroll 1
    for (int d0 = dlo; d0 < dlo + 96; d0 += 8) {
        float xv[8];
#pragma unroll
        for (int q = 0; q < 8; q++) xv[q] = xp[(d0 + q) * LL];
#pragma unroll
        for (int q = 0; q < 8; q++) {
            if (pair == 0) {
#pragma unroll
                for (int j = 0; j < RR; j++)
                    acc[j] = fmaf(wp[j * DD + d0 + q], xv[q], acc[j]);
            } else {
#pragma unroll
                for (int j = 0; j < NS; j++)
                    acc[j] = fmaf(wp[j * DD + d0 + q], xv[q], acc[j]);
            }
        }
    }

    if (half == 1) {
#pragma unroll
        for (int j = 0; j < NS; j++)
            if (j < nch) spart[c0 + j][li] = acc[j];
    }
    __syncthreads();
    if (half == 0) {
#pragma unroll
        for (int j = 0; j < NS; j++)
            if (j < nch) acc[j] += spart[c0 + j][li];
        if (pair == 0) {
#pragma unroll
            for (int j = 0; j < RR; j++) spart[j][li] = acc[j];
        } else {
            float* ob = ((pair == 1) ? g_B : g_C) + (bk * LL + l) * NS;
#pragma unroll
            for (int j = 0; j < 4; j++) {
                float4 v = make_float4(acc[j*4], acc[j*4+1], acc[j*4+2], acc[j*4+3]);
                *reinterpret_cast<float4*>(&ob[j * 4]) = v;
            }
        }
    }
    __syncthreads();

    for (int i = threadIdx.x; i < DD * RR; i += 384)
        pool[i] = dtw[k * DD * RR + i];
    for (int i = threadIdx.x; i < DD; i += 384)
        bd[i] = dtb[k * DD + i];
    __syncthreads();

    float xr[RR];
#pragma unroll
    for (int r = 0; r < RR; r++) xr[r] = spart[r][li];
    int dbase = grp * 32;
#pragma unroll 4
    for (int dd = 0; dd < 32; dd++) {
        int dch = dbase + dd;
        float a = bd[dch];
#pragma unroll
        for (int r = 0; r < RR; r++) a = fmaf(xr[r], pool[dch * RR + r], a);
        g_dt[(bk * DD + dch) * LL + l] = softplusf(a);
    }
}

// ---------------- scan pass 1: per (bkd, n, chunk) local scan ----------------
__global__ void __launch_bounds__(128) k_scan1(const float* __restrict__ alog) {
    int gid = blockIdx.x * blockDim.x + threadIdx.x;
    int n = gid & 15;
    int unit = gid >> 4;
    int chunk = unit & (NCH - 1);
    int bkd = unit >> 4;
    int kd = bkd % (KG * DD);
    float An = -__expf(alog[kd * NS + n]);
    const float* dtp = g_dt + bkd * LL + chunk * CHL;
    const float* up  = g_xs + bkd * LL + chunk * CHL;
    int bk = bkd / DD;
    const float* bp = g_B + (bk * LL + chunk * CHL) * NS + n;
    float h = 0.f, s = 0.f;
#pragma unroll 8
    for (int i = 0; i < CHL; i++) {
        float d_ = dtp[i];
        float u_ = up[i];
        float b_ = bp[i * NS];
        s += d_;
        h = fmaf(h, __expf(d_ * An), d_ * u_ * b_);
    }
    g_hend[gid]  = h;
    g_aprod[gid] = __expf(An * s);
}

// ---------------- scan pass 2: prefix across chunks ----------------
__global__ void k_scan2(void) {
    int t = blockIdx.x * blockDim.x + threadIdx.x;
    int n = t & 15;
    int bkd = t >> 4;
    int base = bkd * (NCH * NS) + n;
    float h = 0.f;
#pragma unroll
    for (int c = 0; c < NCH; c++) {
        g_hin[base + c * NS] = h;
        h = fmaf(g_aprod[base + c * NS], h, g_hend[base + c * NS]);
    }
}

// ---------------- scan pass 3: recompute with prefix, emit y ----------------
__global__ void k_scan3(const float* __restrict__ alog, const float* __restrict__ Ds) {
    int warp_g = blockIdx.x * (blockDim.x / 32) + (threadIdx.x >> 5);
    int lane = threadIdx.x & 31;
    int g = lane >> 4;
    int n = lane & 15;
    int unit = warp_g * 2 + g;
    int chunk = unit & (NCH - 1);
    int bkd = unit >> 4;
    int b = bkd / (KG * DD);
    int kd = bkd % (KG * DD);
    int k = kd / DD, dch = kd % DD;
    float An = -__expf(alog[kd * NS + n]);
    float Dv = Ds[kd];
    float h = g_hin[unit * NS + n];
    const float* dtp = g_dt + bkd * LL + chunk * CHL;
    const float* up  = g_xs + bkd * LL + chunk * CHL;
    int bk = bkd / DD;
    const float* bp = g_B + (bk * LL + chunk * CHL) * NS + n;
    const float* cp = g_C + (bk * LL + chunk * CHL) * NS + n;
    int cglob = k * DD + dch;
#pragma unroll 4
    for (int i = 0; i < CHL; i++) {
        float d_ = dtp[i];
        float u_ = up[i];
        float b_ = bp[i * NS];
        float c_ = cp[i * NS];
        h = fmaf(h, __expf(d_ * An), d_ * u_ * b_);
        float p = h * c_;
        p += __shfl_xor_sync(0xffffffffu, p, 1);
        p += __shfl_xor_sync(0xffffffffu, p, 2);
        p += __shfl_xor_sync(0xffffffffu, p, 4);
        p += __shfl_xor_sync(0xffffffffu, p, 8);
        if (n == 0) {
            int l = chunk * CHL + i;
            int lsp = lsp_of(k, l);
            g_ym[(b * LL + lsp) * CC + cglob] = fmaf(Dv, u_, p);
        }
    }
}

// ---------------- layernorm over C=768, writes bf16 hi/mid split ------------
__global__ void k_ln(const float* __restrict__ w, const float* __restrict__ bia) {
    int row = blockIdx.x;
    const float* yp = g_ym + row * CC;
    int tid = threadIdx.x;
    float s = 0.f, q = 0.f;
#pragma unroll
    for (int c = tid; c < CC; c += 256) {
        float v = yp[c];
        s += v; q = fmaf(v, v, q);
    }
#pragma unroll
    for (int off = 16; off; off >>= 1) {
        s += __shfl_xor_sync(0xffffffffu, s, off);
        q += __shfl_xor_sync(0xffffffffu, q, off);
    }
    __shared__ float ss[8], qq[8];
    int wid = tid >> 5;
    if ((tid & 31) == 0) { ss[wid] = s; qq[wid] = q; }
    __syncthreads();
    if (tid == 0) {
        float S = 0.f, Q = 0.f;
#pragma unroll
        for (int i = 0; i < 8; i++) { S += ss[i]; Q += qq[i]; }
        float mean = S / (float)CC;
        float var = Q / (float)CC - mean * mean;
        ss[0] = mean;
        qq[0] = rsqrtf(var + 1e-5f);
    }
    __syncthreads();
    float mean = ss[0], rstd = qq[0];
#pragma unroll
    for (int c = tid; c < CC; c += 256) {
        float v = fmaf((yp[c] - mean) * rstd, w[c], bia[c]);
        __nv_bfloat16 h = __float2bfloat16(v);
        g_ylh[row * CC + c] = h;
        g_ylm[row * CC + c] = __float2bfloat16(v - __bfloat162float(h));
    }
}

// ---------------- host launcher ----------------
extern "C" void kernel_launch(void* const* d_in, const int* in_sizes, int n_in,
                              void* d_out, int out_size) {
    const float* x    = (const float*)d_in[0];
    const float* ipw  = (const float*)d_in[1];
    const float* cw   = (const float*)d_in[2];
    const float* cb   = (const float*)d_in[3];
    const float* xpw  = (const float*)d_in[4];
    const float* dtw  = (const float*)d_in[5];
    const float* dtb  = (const float*)d_in[6];
    const float* alog = (const float*)d_in[7];
    const float* Ds   = (const float*)d_in[8];
    const float* nw   = (const float*)d_in[9];
    const float* nb   = (const float*)d_in[10];
    const float* opw  = (const float*)d_in[11];
    float* out = (float*)d_out;

    // 0. fused bf16 split of all GEMM operands (float4 vectorized)
    {
        const int q3 = (BL * CIN + CC * CIN + CIN * CC) / 4;
        k_split3<<<(q3 + 255) / 256, 256>>>(x, ipw, opw);
    }
    // 1. in_proj GEMM (bf16 3-split, R8 config)
    {
        dim3 grid(CC / 128, BL / 128);
        k_gemm_in<<<grid, 256>>>();
    }
    // 2. fused conv3x3 + SiLU + gather
    {
        dim3 grid(LL / 32, DD / 32, BSZ * KG);
        dim3 blk(32, 8);
        k_convgather<<<grid, blk>>>(cw, cb);
    }
    // 3. fused x_proj + dt_proj (R9 d-split, 384 threads)
    {
        dim3 grid(LL / 64, BSZ * KG);
        k_xdt<<<grid, 384>>>(xpw, dtw, dtb);
    }
    // 4-6. chunked selective scan
    k_scan1<<<(NBKD * NCH * NS) / 128, 128>>>(alog);
    k_scan2<<<(NBKD * NS) / 128, 128>>>();
    k_scan3<<<(NBKD * NCH) / 2 / 8, 256>>>(alog, Ds);
    // 7. layernorm (emits bf16 split)
    k_ln<<<BL, 256>>>(nw, nb);
    // 8. out_proj GEMM (bf16 3-split, R8 config)
    {
        dim3 grid(CIN / 128, BL / 64);
        k_gemm_out<<<grid, 128>>>(out);
    }
}

// round 15
// speedup vs baseline: 1.5787x; 1.0333x over previous
#include <cuda_runtime.h>
#include <cuda_bf16.h>
#include <math.h>
#include <stdint.h>

// ---------------- problem constants ----------------
#define BSZ 2
#define HH  48
#define WW  48
#define LL  (HH*WW)          // 2304
#define CIN 384              // 2*D_MODEL
#define CC  768              // C_INNER
#define KG  4
#define DD  192              // D_IN
#define NS  16
#define RR  12
#define CDBL 44              // R + 2N
#define BL  (BSZ*LL)         // 4608
#define NCH 16
#define CHL (LL/NCH)         // 144
#define NBKD (BSZ*KG*DD)     // 1536

// ---------------- device scratch ----------------
__device__ float g_xz  [BL*CC];          // in_proj output, [B*L, 768] channel-last
__device__ float g_xs  [BSZ*KG*DD*LL];   // scan inputs u, [bkd][L]
__device__ float g_B   [BSZ*KG*LL*NS];   // B, [bk][l][n]  (n fastest)
__device__ float g_C   [BSZ*KG*LL*NS];   // C, [bk][l][n]
__device__ float g_dt  [BSZ*KG*DD*LL];   // softplus(dt), [bkd][L]
__device__ float g_hend [NBKD*NCH*NS];
__device__ float g_aprod[NBKD*NCH*NS];
__device__ float g_hin  [NBKD*NCH*NS];
__device__ float g_ym  [BL*CC];          // y merged spatially, [B*L, 768]

// bf16 split operand buffers for tensor-core GEMMs
__device__ __nv_bfloat16 g_xh [BL*CIN],  g_xm [BL*CIN];   // x split
__device__ __nv_bfloat16 g_wih[CC*CIN],  g_wim[CC*CIN];   // in_proj_w split
__device__ __nv_bfloat16 g_woh[CIN*CC],  g_wom[CIN*CC];   // out_proj_w split
__device__ __nv_bfloat16 g_ylh[BL*CC],   g_ylm[BL*CC];    // layernorm output split

// scan-order index -> spatial index, per direction k
__device__ __forceinline__ int lsp_of(int k, int l) {
    switch (k) {
        case 0:  return l;
        case 1:  return (l % HH) * WW + (l / HH);
        case 2:  return LL - 1 - l;
        default: { int l2 = LL - 1 - l; return (l2 % HH) * WW + (l2 / HH); }
    }
}

__device__ __forceinline__ float softplusf(float x) {
    return (x > 15.f) ? x : log1pf(__expf(x));
}

__device__ __forceinline__ uint32_t smem_u32(const void* p) {
    return (uint32_t)__cvta_generic_to_shared(p);
}

__device__ __forceinline__ void cp16(uint32_t saddr, const void* g) {
    asm volatile("cp.async.cg.shared.global [%0], [%1], 16;" :: "r"(saddr), "l"(g));
}
__device__ __forceinline__ void cp_commit() {
    asm volatile("cp.async.commit_group;");
}
__device__ __forceinline__ void cp_wait1() {
    asm volatile("cp.async.wait_group 1;");
}

// ---------------- fused bf16 split, float4 vectorized ----------------------
__global__ void k_split3(const float* __restrict__ x,
                         const float* __restrict__ ipw,
                         const float* __restrict__ opw) {
    const int q1 = (BL * CIN) / 4, q2 = q1 + (CC * CIN) / 4, q3 = q2 + (CIN * CC) / 4;
    int i = blockIdx.x * blockDim.x + threadIdx.x;
    if (i >= q3) return;
    const float* s; __nv_bfloat16 *hp, *mp; int off;
    if (i < q1)      { s = x;   hp = g_xh;  mp = g_xm;  off = i; }
    else if (i < q2) { s = ipw; hp = g_wih; mp = g_wim; off = i - q1; }
    else             { s = opw; hp = g_woh; mp = g_wom; off = i - q2; }
    float4 v = reinterpret_cast<const float4*>(s)[off];
    float vv[4] = {v.x, v.y, v.z, v.w};
    __nv_bfloat16 h4[4], m4[4];
#pragma unroll
    for (int j = 0; j < 4; j++) {
        h4[j] = __float2bfloat16(vv[j]);
        m4[j] = __float2bfloat16(vv[j] - __bfloat162float(h4[j]));
    }
    reinterpret_cast<uint2*>(hp)[off] = *reinterpret_cast<uint2*>(h4);
    reinterpret_cast<uint2*>(mp)[off] = *reinterpret_cast<uint2*>(m4);
}

// ---------------- bf16 3-split tensor-core GEMM (NT) ------------------------
// C[M,N]=A*B^T via Ah*Bh + Ah*Bm + Am*Bh, fp32 accum.
// Warp tile 64x32 (MT=4 x NT=4), ldmatrix frags, cp.async 2-stage pipeline.
// R15: smaller tiles -> 432-CTA grids for wave balance on 148 SMs.

#define SROW 12   // smem row stride in words (8 data + 4 pad)

#define MMA_BF16(C, a0,a1,a2,a3, b0,b1) \
    asm volatile("mma.sync.aligned.m16n8k16.row.col.f32.bf16.bf16.f32 " \
        "{%0,%1,%2,%3},{%4,%5,%6,%7},{%8,%9},{%0,%1,%2,%3};" \
        : "+f"(C[0]), "+f"(C[1]), "+f"(C[2]), "+f"(C[3]) \
        : "r"(a0), "r"(a1), "r"(a2), "r"(a3), "r"(b0), "r"(b1))

#define LDSM4(r0,r1,r2,r3,addr) \
    asm volatile("ldmatrix.sync.aligned.m8n8.x4.shared.b16 {%0,%1,%2,%3}, [%4];" \
        : "=r"(r0), "=r"(r1), "=r"(r2), "=r"(r3) : "r"(addr))

template<int BM, int BN, int NTHR, int WR>
__device__ __forceinline__ void gemm_body(int N, int Kd,
        const __nv_bfloat16* __restrict__ Ahp, const __nv_bfloat16* __restrict__ Amp,
        const __nv_bfloat16* __restrict__ Bhp, const __nv_bfloat16* __restrict__ Bmp,
        float* __restrict__ Co) {
    constexpr int MT = BM / (WR * 16);      // 4
    __shared__ uint32_t sAh[2][BM * SROW], sAm[2][BM * SROW];
    __shared__ uint32_t sBh[2][BN * SROW], sBm[2][BN * SROW];

    const int tid  = threadIdx.x;
    const int lane = tid & 31;
    const int wid  = tid >> 5;
    const int g    = lane >> 2;
    const int t    = lane & 3;
    const int wm   = (wid % WR) * (MT * 16);
    const int wn   = (wid / WR) * 32;
    const int bm0  = blockIdx.y * BM;
    const int bn0  = blockIdx.x * BN;
    const int Kw   = Kd >> 1;

    const uint32_t* gAh = (const uint32_t*)Ahp;
    const uint32_t* gAm = (const uint32_t*)Amp;
    const uint32_t* gBh = (const uint32_t*)Bhp;
    const uint32_t* gBm = (const uint32_t*)Bmp;

    const int lrow8 = ((lane >> 3) & 1) * 8 + (lane & 7);
    const int loff  = (lane >> 4) * 4;

    float acc[MT][4][4];
#pragma unroll
    for (int mt = 0; mt < MT; mt++)
#pragma unroll
        for (int nt = 0; nt < 4; nt++)
#pragma unroll
            for (int j = 0; j < 4; j++) acc[mt][nt][j] = 0.f;

    auto load_stage = [&](int kt, int st) {
        const int k0w = kt * 8;
#pragma unroll
        for (int idx = tid; idx < 2 * (BM + BN); idx += NTHR) {
            int half = idx & 1, r = idx >> 1;
            if (r < BM) {
                cp16(smem_u32(&sAh[st][r * SROW + half * 4]),
                     &gAh[(bm0 + r) * Kw + k0w + half * 4]);
                cp16(smem_u32(&sAm[st][r * SROW + half * 4]),
                     &gAm[(bm0 + r) * Kw + k0w + half * 4]);
            } else {
                int rb = r - BM;
                cp16(smem_u32(&sBh[st][rb * SROW + half * 4]),
                     &gBh[(bn0 + rb) * Kw + k0w + half * 4]);
                cp16(smem_u32(&sBm[st][rb * SROW + half * 4]),
                     &gBm[(bn0 + rb) * Kw + k0w + half * 4]);
            }
        }
    };

    const int NKT = Kw / 8;
    load_stage(0, 0);
    cp_commit();

    for (int kt = 0; kt < NKT; kt++) {
        int st = kt & 1;
        if (kt + 1 < NKT) load_stage(kt + 1, st ^ 1);
        cp_commit();
        cp_wait1();
        __syncthreads();

        uint32_t bh[4][2], bl[4][2];
#pragma unroll
        for (int np = 0; np < 2; np++) {
            uint32_t r0, r1, r2, r3;
            LDSM4(r0, r1, r2, r3, smem_u32(&sBh[st][(wn + np * 16 + lrow8) * SROW + loff]));
            bh[np*2][0] = r0; bh[np*2+1][0] = r1; bh[np*2][1] = r2; bh[np*2+1][1] = r3;
            LDSM4(r0, r1, r2, r3, smem_u32(&sBm[st][(wn + np * 16 + lrow8) * SROW + loff]));
            bl[np*2][0] = r0; bl[np*2+1][0] = r1; bl[np*2][1] = r2; bl[np*2+1][1] = r3;
        }
#pragma unroll
        for (int mt = 0; mt < MT; mt++) {
            uint32_t ah0, ah1, ah2, ah3, am0, am1, am2, am3;
            LDSM4(ah0, ah1, ah2, ah3, smem_u32(&sAh[st][(wm + mt * 16 + lrow8) * SROW + loff]));
            LDSM4(am0, am1, am2, am3, smem_u32(&sAm[st][(wm + mt * 16 + lrow8) * SROW + loff]));
#pragma unroll
            for (int nt = 0; nt < 4; nt++) {
                MMA_BF16(acc[mt][nt], ah0, ah1, ah2, ah3, bh[nt][0], bh[nt][1]);
                MMA_BF16(acc[mt][nt], ah0, ah1, ah2, ah3, bl[nt][0], bl[nt][1]);
                MMA_BF16(acc[mt][nt], am0, am1, am2, am3, bh[nt][0], bh[nt][1]);
            }
        }
        __syncthreads();
    }

#pragma unroll
    for (int mt = 0; mt < MT; mt++) {
#pragma unroll
        for (int nt = 0; nt < 4; nt++) {
            int row0 = bm0 + wm + mt * 16 + g;
            int col  = bn0 + wn + nt * 8 + t * 2;
            *reinterpret_cast<float2*>(&Co[row0 * N + col]) =
                make_float2(acc[mt][nt][0], acc[mt][nt][1]);
            *reinterpret_cast<float2*>(&Co[(row0 + 8) * N + col]) =
                make_float2(acc[mt][nt][2], acc[mt][nt][3]);
        }
    }
}

// gemm_in: 128x64 tiles, 128 thr (WR=2, 2 warps N) -> grid 12x36 = 432 CTAs
__global__ void __launch_bounds__(128, 4) k_gemm_in(void) {
    gemm_body<128, 64, 128, 2>(CC, CIN, g_xh, g_xm, g_wih, g_wim, g_xz);
}
// gemm_out: 64x64 tiles, 64 thr (WR=1, 2 warps N) -> grid 6x72 = 432 CTAs
__global__ void __launch_bounds__(64, 8) k_gemm_out(float* __restrict__ Co) {
    gemm_body<64, 64, 64, 1>(CIN, CC, g_ylh, g_ylm, g_woh, g_wom, Co);
}

// ---------------- fused depthwise conv3x3 + SiLU + gather to scan order -----
__global__ void k_convgather(const float* __restrict__ cw, const float* __restrict__ cb) {
    __shared__ float t[32][33];
    int bk = blockIdx.z;
    int b = bk / KG, k = bk % KG;
    int l0 = blockIdx.x * 32;
    int d0 = blockIdx.y * 32;
    int tx = threadIdx.x, ty = threadIdx.y;
    int c = k * DD + d0 + tx;
    float w9[9];
#pragma unroll
    for (int i = 0; i < 9; i++) w9[i] = cw[c * 9 + i];
    float bias = cb[c];
#pragma unroll
    for (int r = 0; r < 4; r++) {
        int lq = l0 + ty + r * 8;
        int lsp = lsp_of(k, lq);
        int h = lsp / WW, w = lsp % WW;
        float acc = bias;
#pragma unroll
        for (int dh = 0; dh < 3; dh++) {
            int hh = h + dh - 1;
            if (hh < 0 || hh >= HH) continue;
#pragma unroll
            for (int dw = 0; dw < 3; dw++) {
                int ww2 = w + dw - 1;
                if (ww2 < 0 || ww2 >= WW) continue;
                acc = fmaf(g_xz[(b * LL + hh * WW + ww2) * CC + c], w9[dh * 3 + dw], acc);
            }
        }
        float sg = 1.f / (1.f + __expf(-acc));
        t[tx][ty + r * 8] = acc * sg;
    }
    __syncthreads();
#pragma unroll
    for (int r = 0; r < 4; r++) {
        int dq = ty + r * 8;
        g_xs[(bk * DD + d0 + dq) * LL + l0 + tx] = t[dq][tx];
    }
}

// ---------------- fused x_proj + dt_proj, d-split (R9 measured-best) --------
__global__ void __launch_bounds__(384) k_xdt(const float* __restrict__ xpw,
                                             const float* __restrict__ dtw,
                                             const float* __restrict__ dtb) {
    __shared__ float pool[CDBL * DD];     // 33 KB: ws in phase A, wd in phase B
    __shared__ float spart[CDBL][64];     // 11 KB
    __shared__ float bd[DD];
    int bk = blockIdx.y;
    int k = bk % KG;
    for (int i = threadIdx.x; i < CDBL * DD; i += 384)
        pool[i] = xpw[k * CDBL * DD + i];
    __syncthreads();

    int grp  = threadIdx.x / 64;          // 0..5
    int li   = threadIdx.x % 64;
    int pair = grp % 3;                   // 0 dts, 1 B, 2 C
    int half = grp / 3;
    int l    = blockIdx.x * 64 + li;
    int nch  = (pair == 0) ? RR : NS;
    int c0   = (pair == 0) ? 0 : (RR + (pair - 1) * NS);
    const float* xp = g_xs + bk * DD * LL + l;
    const float* wp = pool + c0 * DD;
    int dlo = half * 96;

    float acc[NS];
#pragma unroll
    for (int j = 0; j < NS; j++) acc[j] = 0.f;
#pragma unroll 1
    for (int d0 = dlo; d0 < dlo + 96; d0 += 8) {
        float xv[8];
#pragma unroll
        for (int q = 0; q < 8; q++) xv[q] = xp[(d0 + q) * LL];
#pragma unroll
        for (int q = 0; q < 8; q++) {
            if (pair == 0) {
#pragma unroll
                for (int j = 0; j < RR; j++)
                    acc[j] = fmaf(wp[j * DD + d0 + q], xv[q], acc[j]);
            } else {
#pragma unroll
                for (int j = 0; j < NS; j++)
                    acc[j] = fmaf(wp[j * DD + d0 + q], xv[q], acc[j]);
            }
        }
    }

    if (half == 1) {
#pragma unroll
        for (int j = 0; j < NS; j++)
            if (j < nch) spart[c0 + j][li] = acc[j];
    }
    __syncthreads();
    if (half == 0) {
#pragma unroll
        for (int j = 0; j < NS; j++)
            if (j < nch) acc[j] += spart[c0 + j][li];
        if (pair == 0) {
#pragma unroll
            for (int j = 0; j < RR; j++) spart[j][li] = acc[j];
        } else {
            float* ob = ((pair == 1) ? g_B : g_C) + (bk * LL + l) * NS;
#pragma unroll
            for (int j = 0; j < 4; j++) {
                float4 v = make_float4(acc[j*4], acc[j*4+1], acc[j*4+2], acc[j*4+3]);
                *reinterpret_cast<float4*>(&ob[j * 4]) = v;
            }
        }
    }
    __syncthreads();

    for (int i = threadIdx.x; i < DD * RR; i += 384)
        pool[i] = dtw[k * DD * RR + i];
    for (int i = threadIdx.x; i < DD; i += 384)
        bd[i] = dtb[k * DD + i];
    __syncthreads();

    float xr[RR];
#pragma unroll
    for (int r = 0; r < RR; r++) xr[r] = spart[r][li];
    int dbase = grp * 32;
#pragma unroll 4
    for (int dd = 0; dd < 32; dd++) {
        int dch = dbase + dd;
        float a = bd[dch];
#pragma unroll
        for (int r = 0; r < RR; r++) a = fmaf(xr[r], pool[dch * RR + r], a);
        g_dt[(bk * DD + dch) * LL + l] = softplusf(a);
    }
}

// ---------------- scan pass 1: per (bkd, n, chunk) local scan ----------------
__global__ void __launch_bounds__(128) k_scan1(const float* __restrict__ alog) {
    int gid = blockIdx.x * blockDim.x + threadIdx.x;
    int n = gid & 15;
    int unit = gid >> 4;
    int chunk = unit & (NCH - 1);
    int bkd = unit >> 4;
    int kd = bkd % (KG * DD);
    float An = -__expf(alog[kd * NS + n]);
    const float* dtp = g_dt + bkd * LL + chunk * CHL;
    const float* up  = g_xs + bkd * LL + chunk * CHL;
    int bk = bkd / DD;
    const float* bp = g_B + (bk * LL + chunk * CHL) * NS + n;
    float h = 0.f, s = 0.f;
#pragma unroll 8
    for (int i = 0; i < CHL; i++) {
        float d_ = dtp[i];
        float u_ = up[i];
        float b_ = bp[i * NS];
        s += d_;
        h = fmaf(h, __expf(d_ * An), d_ * u_ * b_);
    }
    g_hend[gid]  = h;
    g_aprod[gid] = __expf(An * s);
}

// ---------------- scan pass 2: prefix across chunks ----------------
__global__ void k_scan2(void) {
    int t = blockIdx.x * blockDim.x + threadIdx.x;
    int n = t & 15;
    int bkd = t >> 4;
    int base = bkd * (NCH * NS) + n;
    float h = 0.f;
#pragma unroll
    for (int c = 0; c < NCH; c++) {
        g_hin[base + c * NS] = h;
        h = fmaf(g_aprod[base + c * NS], h, g_hend[base + c * NS]);
    }
}

// ---------------- scan pass 3: recompute with prefix, emit y ----------------
__global__ void k_scan3(const float* __restrict__ alog, const float* __restrict__ Ds) {
    int warp_g = blockIdx.x * (blockDim.x / 32) + (threadIdx.x >> 5);
    int lane = threadIdx.x & 31;
    int g = lane >> 4;
    int n = lane & 15;
    int unit = warp_g * 2 + g;
    int chunk = unit & (NCH - 1);
    int bkd = unit >> 4;
    int b = bkd / (KG * DD);
    int kd = bkd % (KG * DD);
    int k = kd / DD, dch = kd % DD;
    float An = -__expf(alog[kd * NS + n]);
    float Dv = Ds[kd];
    float h = g_hin[unit * NS + n];
    const float* dtp = g_dt + bkd * LL + chunk * CHL;
    const float* up  = g_xs + bkd * LL + chunk * CHL;
    int bk = bkd / DD;
    const float* bp = g_B + (bk * LL + chunk * CHL) * NS + n;
    const float* cp = g_C + (bk * LL + chunk * CHL) * NS + n;
    int cglob = k * DD + dch;
#pragma unroll 4
    for (int i = 0; i < CHL; i++) {
        float d_ = dtp[i];
        float u_ = up[i];
        float b_ = bp[i * NS];
        float c_ = cp[i * NS];
        h = fmaf(h, __expf(d_ * An), d_ * u_ * b_);
        float p = h * c_;
        p += __shfl_xor_sync(0xffffffffu, p, 1);
        p += __shfl_xor_sync(0xffffffffu, p, 2);
        p += __shfl_xor_sync(0xffffffffu, p, 4);
        p += __shfl_xor_sync(0xffffffffu, p, 8);
        if (n == 0) {
            int l = chunk * CHL + i;
            int lsp = lsp_of(k, l);
            g_ym[(b * LL + lsp) * CC + cglob] = fmaf(Dv, u_, p);
        }
    }
}

// ---------------- layernorm over C=768, writes bf16 hi/mid split ------------
__global__ void k_ln(const float* __restrict__ w, const float* __restrict__ bia) {
    int row = blockIdx.x;
    const float* yp = g_ym + row * CC;
    int tid = threadIdx.x;
    float s = 0.f, q = 0.f;
#pragma unroll
    for (int c = tid; c < CC; c += 256) {
        float v = yp[c];
        s += v; q = fmaf(v, v, q);
    }
#pragma unroll
    for (int off = 16; off; off >>= 1) {
        s += __shfl_xor_sync(0xffffffffu, s, off);
        q += __shfl_xor_sync(0xffffffffu, q, off);
    }
    __shared__ float ss[8], qq[8];
    int wid = tid >> 5;
    if ((tid & 31) == 0) { ss[wid] = s; qq[wid] = q; }
    __syncthreads();
    if (tid == 0) {
        float S = 0.f, Q = 0.f;
#pragma unroll
        for (int i = 0; i < 8; i++) { S += ss[i]; Q += qq[i]; }
        float mean = S / (float)CC;
        float var = Q / (float)CC - mean * mean;
        ss[0] = mean;
        qq[0] = rsqrtf(var + 1e-5f);
    }
    __syncthreads();
    float mean = ss[0], rstd = qq[0];
#pragma unroll
    for (int c = tid; c < CC; c += 256) {
        float v = fmaf((yp[c] - mean) * rstd, w[c], bia[c]);
        __nv_bfloat16 h = __float2bfloat16(v);
        g_ylh[row * CC + c] = h;
        g_ylm[row * CC + c] = __float2bfloat16(v - __bfloat162float(h));
    }
}

// ---------------- host launcher ----------------
extern "C" void kernel_launch(void* const* d_in, const int* in_sizes, int n_in,
                              void* d_out, int out_size) {
    const float* x    = (const float*)d_in[0];
    const float* ipw  = (const float*)d_in[1];
    const float* cw   = (const float*)d_in[2];
    const float* cb   = (const float*)d_in[3];
    const float* xpw  = (const float*)d_in[4];
    const float* dtw  = (const float*)d_in[5];
    const float* dtb  = (const float*)d_in[6];
    const float* alog = (const float*)d_in[7];
    const float* Ds   = (const float*)d_in[8];
    const float* nw   = (const float*)d_in[9];
    const float* nb   = (const float*)d_in[10];
    const float* opw  = (const float*)d_in[11];
    float* out = (float*)d_out;

    // 0. fused bf16 split of all GEMM operands (float4 vectorized)
    {
        const int q3 = (BL * CIN + CC * CIN + CIN * CC) / 4;
        k_split3<<<(q3 + 255) / 256, 256>>>(x, ipw, opw);
    }
    // 1. in_proj GEMM: 432 CTAs for wave balance
    {
        dim3 grid(CC / 64, BL / 128);
        k_gemm_in<<<grid, 128>>>();
    }
    // 2. fused conv3x3 + SiLU + gather
    {
        dim3 grid(LL / 32, DD / 32, BSZ * KG);
        dim3 blk(32, 8);
        k_convgather<<<grid, blk>>>(cw, cb);
    }
    // 3. fused x_proj + dt_proj (R9 d-split, 384 threads)
    {
        dim3 grid(LL / 64, BSZ * KG);
        k_xdt<<<grid, 384>>>(xpw, dtw, dtb);
    }
    // 4-6. chunked selective scan
    k_scan1<<<(NBKD * NCH * NS) / 128, 128>>>(alog);
    k_scan2<<<(NBKD * NS) / 128, 128>>>();
    k_scan3<<<(NBKD * NCH) / 2 / 8, 256>>>(alog, Ds);
    // 7. layernorm (emits bf16 split)
    k_ln<<<BL, 256>>>(nw, nb);
    // 8. out_proj GEMM: 432 CTAs for wave balance
    {
        dim3 grid(CIN / 64, BL / 64);
        k_gemm_out<<<grid, 64>>>(out);
    }
}